// round 5
// baseline (speedup 1.0000x reference)
#include <cuda_runtime.h>
#include <cuda_fp16.h>
#include <cuda_fp8.h>

#define SEQ 2048
#define H 1024
#define L 4
#define NSTEPS (SEQ + L - 1)
#define NBLOCKS 148
#define NTHREADS 512

#define HFRAG_BYTES 4096
#define SMEM_MAX (HFRAG_BYTES + 204800)   // 208896 B worst case

// ------------------------- device scratch (no allocs) -------------------------
// B-fragment-packed fp8 weights.
// layer0 pairs (512): W frag only, 1024 uint2 each (8 KB)
// layers1-3 pairs (1536): W frag (1024 uint2) then UH frag (1024 uint2), 16 KB
__device__ uint2 g_frag0[512 * 1024];
__device__ uint2 g_fragH[1536 * 2048];
__device__ float g_Zin[(size_t)SEQ * 4 * H];
__device__ __align__(16) unsigned char g_h8[2][4 * 1024]; // fp8 h, frag layout, dbl-buf
__device__ unsigned g_bar_count;
__device__ unsigned g_bar_gen;

// ------------------------- helpers --------------------------------------------
__device__ __forceinline__ const float* sel4(int g, const float* a, const float* b,
                                             const float* c, const float* d)
{ return g == 0 ? a : g == 1 ? b : g == 2 ? c : d; }

__device__ __forceinline__ unsigned pack_fp8x4(const float* s)
{
    unsigned v = 0;
#pragma unroll
    for (int j = 0; j < 4; ++j)
        v |= (unsigned)__nv_cvt_float_to_fp8(s[j], __NV_SATFINITE, __NV_E4M3) << (8 * j);
    return v;
}

// ------------------------- weight fragment pack --------------------------------
// B frag (k32n8 col-major, e4m3): lane = gid*4+tig; b0 = col gid, k = kc*32+tig*4..+3
//                                               b1 = col gid, k = +16..+19
// col = 2*gate + rowsel   (gate 0..3 = f,g,q,cand; rowsel 0/1 = row i0/i0+1)
__global__ void prep_frag(const float* __restrict__ Wf, const float* __restrict__ Wg,
                          const float* __restrict__ Wq, const float* __restrict__ Wc,
                          const float* __restrict__ UHf, const float* __restrict__ UHg,
                          const float* __restrict__ UHq, const float* __restrict__ UHc)
{
    size_t idx = (size_t)blockIdx.x * blockDim.x + threadIdx.x;
    const size_t N0 = 512u * 1024u;
    const size_t NH = 1536u * 2048u;
    if (idx < N0) {
        int p = (int)(idx >> 10);
        int r = (int)(idx & 1023);
        int kc = r >> 5, lane = r & 31;
        int gid = lane >> 2, tig = lane & 3;
        int gate = gid >> 1, rsel = gid & 1;
        int i = 2 * p + rsel;
        const float* src = sel4(gate, Wf, Wg, Wq, Wc) + (size_t)i * H;  // layer 0
        int k0 = kc * 32 + tig * 4;
        g_frag0[idx] = make_uint2(pack_fp8x4(src + k0), pack_fp8x4(src + k0 + 16));
    } else if (idx < N0 + NH) {
        size_t j = idx - N0;
        int p = (int)(j >> 11);
        int r = (int)(j & 2047);
        int which = r >> 10; r &= 1023;
        int kc = r >> 5, lane = r & 31;
        int gid = lane >> 2, tig = lane & 3;
        int gate = gid >> 1, rsel = gid & 1;
        int l = 1 + (p >> 9);
        int i = 2 * (p & 511) + rsel;
        const float* src;
        if (which == 0) src = sel4(gate, Wf, Wg, Wq, Wc) + ((size_t)l * H + i) * H;
        else            src = sel4(gate, UHf, UHg, UHq, UHc) + ((size_t)(l - 1) * H + i) * H;
        int k0 = kc * 32 + tig * 4;
        g_fragH[j] = make_uint2(pack_fp8x4(src + k0), pack_fp8x4(src + k0 + 16));
    }
}

__global__ void init_state()
{
    int tid = threadIdx.x;
    for (int i = tid; i < 2 * 4 * 1024; i += blockDim.x) {
        g_h8[0][i & 4095] = 0;           // covers both buffers below
    }
    for (int i = tid; i < 4 * 1024; i += blockDim.x) {
        g_h8[0][i] = 0; g_h8[1][i] = 0;
    }
    if (tid == 0) { g_bar_count = 0u; g_bar_gen = 0u; }
}

// ------------------------- Zin GEMM: C[t][g*H+i] = sum_k x[t][k] * U_g[i][k] ---
#define BM 128
#define BN 128
#define BK 16
__global__ __launch_bounds__(256) void gemm_zin(
    const float* __restrict__ A,
    const float* __restrict__ U0, const float* __restrict__ U1,
    const float* __restrict__ U2, const float* __restrict__ U3)
{
    __shared__ __align__(16) float As[BK][BM];
    __shared__ __align__(16) float Bs[BK][BN];
    const int tid = threadIdx.x;
    const int bm = blockIdx.y * BM;
    const int bn = blockIdx.x * BN;
    const int gate = bn >> 10;
    const float* Bp = ((gate == 0) ? U0 : (gate == 1) ? U1 : (gate == 2) ? U2 : U3)
                      + (size_t)(bn & (H - 1)) * H;
    const int lr = tid & 63;
    const int gq = tid >> 6;
    const int tx = tid & 15, ty = tid >> 4;

    float acc[8][8];
#pragma unroll
    for (int i = 0; i < 8; ++i)
#pragma unroll
        for (int j = 0; j < 8; ++j) acc[i][j] = 0.f;

    for (int k0 = 0; k0 < H; k0 += BK) {
        float4 a0 = *(const float4*)(A + (size_t)(bm + lr) * H + k0 + gq * 4);
        float4 a1 = *(const float4*)(A + (size_t)(bm + lr + 64) * H + k0 + gq * 4);
        float4 b0 = *(const float4*)(Bp + (size_t)lr * H + k0 + gq * 4);
        float4 b1 = *(const float4*)(Bp + (size_t)(lr + 64) * H + k0 + gq * 4);
        As[gq * 4 + 0][lr] = a0.x; As[gq * 4 + 1][lr] = a0.y;
        As[gq * 4 + 2][lr] = a0.z; As[gq * 4 + 3][lr] = a0.w;
        As[gq * 4 + 0][lr + 64] = a1.x; As[gq * 4 + 1][lr + 64] = a1.y;
        As[gq * 4 + 2][lr + 64] = a1.z; As[gq * 4 + 3][lr + 64] = a1.w;
        Bs[gq * 4 + 0][lr] = b0.x; Bs[gq * 4 + 1][lr] = b0.y;
        Bs[gq * 4 + 2][lr] = b0.z; Bs[gq * 4 + 3][lr] = b0.w;
        Bs[gq * 4 + 0][lr + 64] = b1.x; Bs[gq * 4 + 1][lr + 64] = b1.y;
        Bs[gq * 4 + 2][lr + 64] = b1.z; Bs[gq * 4 + 3][lr + 64] = b1.w;
        __syncthreads();
#pragma unroll
        for (int kk = 0; kk < BK; ++kk) {
            float4 a0r = *(const float4*)&As[kk][ty * 8];
            float4 a1r = *(const float4*)&As[kk][ty * 8 + 4];
            float4 b0r = *(const float4*)&Bs[kk][tx * 8];
            float4 b1r = *(const float4*)&Bs[kk][tx * 8 + 4];
            float ar[8] = {a0r.x, a0r.y, a0r.z, a0r.w, a1r.x, a1r.y, a1r.z, a1r.w};
            float br[8] = {b0r.x, b0r.y, b0r.z, b0r.w, b1r.x, b1r.y, b1r.z, b1r.w};
#pragma unroll
            for (int i = 0; i < 8; ++i)
#pragma unroll
                for (int j = 0; j < 8; ++j)
                    acc[i][j] = fmaf(ar[i], br[j], acc[i][j]);
        }
        __syncthreads();
    }
#pragma unroll
    for (int i = 0; i < 8; ++i) {
        int m = bm + ty * 8 + i;
        float* crow = g_Zin + (size_t)m * (4 * H) + bn + tx * 8;
#pragma unroll
        for (int j = 0; j < 8; j += 4) {
            *(float4*)(crow + j) = make_float4(acc[i][j], acc[i][j + 1],
                                               acc[i][j + 2], acc[i][j + 3]);
        }
    }
}

// ------------------------- grid barrier (release/acquire, no fence) -----------
__device__ __forceinline__ void grid_barrier()
{
    __syncthreads();
    if (threadIdx.x == 0) {
        unsigned gen;
        asm volatile("ld.relaxed.gpu.u32 %0, [%1];" : "=r"(gen)
                     : "l"(&g_bar_gen) : "memory");
        unsigned arrived;
        asm volatile("atom.release.gpu.add.u32 %0, [%1], 1;" : "=r"(arrived)
                     : "l"(&g_bar_count) : "memory");
        if (arrived == NBLOCKS - 1) {
            g_bar_count = 0u;
            asm volatile("st.release.gpu.u32 [%0], %1;" ::
                         "l"(&g_bar_gen), "r"(gen + 1u) : "memory");
        } else {
            unsigned cur;
            do {
                asm volatile("ld.acquire.gpu.u32 %0, [%1];" : "=r"(cur)
                             : "l"(&g_bar_gen) : "memory");
            } while (cur == gen);
        }
    }
    __syncthreads();
}

// ------------------------- fp8 warp MMA -----------------------------------------
// D[16x8] += A[16x32] * B[32x8]; A rows replicated (a1=a0, a3=a2) -> row 0 valid.
__device__ __forceinline__ void mma_fp8(float d[4], unsigned alo, unsigned ahi,
                                        unsigned b0, unsigned b1)
{
    asm volatile(
        "mma.sync.aligned.m16n8k32.row.col.f32.e4m3.e4m3.f32 "
        "{%0,%1,%2,%3}, {%4,%5,%6,%7}, {%8,%9}, {%0,%1,%2,%3};\n"
        : "+f"(d[0]), "+f"(d[1]), "+f"(d[2]), "+f"(d[3])
        : "r"(alo), "r"(alo), "r"(ahi), "r"(ahi), "r"(b0), "r"(b1));
}

// ------------------------- persistent wavefront LSTM (fp8 MMA) -----------------
__global__ __launch_bounds__(NTHREADS, 1) void lstm_main(
    const float* __restrict__ Bf, const float* __restrict__ Bg,
    const float* __restrict__ Bq, const float* __restrict__ Bc,
    float* __restrict__ out)
{
    extern __shared__ __align__(16) unsigned char smem[];
    uint2* sh_hfrag = reinterpret_cast<uint2*>(smem);  // [4 layers][128] uint2

    const int tid = threadIdx.x;
    const int lane = tid & 31;
    const int w = tid >> 5;
    const int b = blockIdx.x;
    const int tig = lane & 3;

    // ---- block task partition: l0 pairs and l>0 pairs ----
    const int n0 = (b < 68) ? 4 : 3;
    const int s0 = (b < 68) ? 4 * b : 272 + 3 * (b - 68);
    int nh, sh0;
    if (b < 68)       { nh = 10; sh0 = 10 * b; }
    else if (b < 124) { nh = 11; sh0 = 680 + 11 * (b - 68); }
    else              { nh = 10; sh0 = 1296 + 10 * (b - 124); }

    int l = 0, i0 = 0;
    bool valid = false, isl0 = false;
    size_t woff = HFRAG_BYTES;
    if (w < n0) {
        valid = true; isl0 = true; l = 0;
        int p = s0 + w;
        i0 = 2 * p;
        woff = HFRAG_BYTES + (size_t)w * 8192;
        const uint4* src = reinterpret_cast<const uint4*>(g_frag0 + (size_t)p * 1024);
        uint4* dst = reinterpret_cast<uint4*>(smem + woff);
#pragma unroll 4
        for (int m = lane; m < 512; m += 32) dst[m] = __ldcg(src + m);
    } else if (w < n0 + nh) {
        valid = true;
        int p = sh0 + (w - n0);
        l = 1 + (p >> 9);
        i0 = 2 * (p & 511);
        woff = HFRAG_BYTES + (size_t)n0 * 8192 + (size_t)(w - n0) * 16384;
        const uint4* src = reinterpret_cast<const uint4*>(g_fragH + (size_t)p * 2048);
        uint4* dst = reinterpret_cast<uint4*>(smem + woff);
#pragma unroll 4
        for (int m = lane; m < 1024; m += 32) dst[m] = __ldcg(src + m);
    }

    // per-lane epilogue constants (lanes 0,1 finalize rows i0, i0+1)
    const int myi = i0 + (lane & 1);
    const int bi = l * H + myi;
    float bfv = 0.f, bgv = 0.f, bqv = 0.f, bcv = 0.f;
    if (valid && lane < 2) { bfv = Bf[bi]; bgv = Bg[bi]; bqv = Bq[bi]; bcv = Bc[bi]; }
    const int r5 = myi & 31;
    const int fragoff = l * 1024 + ((myi >> 5) * 4 + ((r5 & 15) >> 2)) * 8
                        + (r5 >> 4) * 4 + (myi & 3);
    float s_state = 0.f;

    const uint2* bwp = reinterpret_cast<const uint2*>(smem + woff);
    const uint2* bup = bwp + 1024;
    const uint2* haW = sh_hfrag + l * 128;
    const uint2* haU = sh_hfrag + (l > 0 ? l - 1 : 0) * 128;

    __syncthreads();

    for (int step = 0; step < NSTEPS; ++step) {
        // stage 4 KB of fp8 h-fragments (written at step-1)
        sh_hfrag[tid] = __ldcg(reinterpret_cast<const uint2*>(g_h8[step & 1]) + tid);
        __syncthreads();

        const int t = step - l;
        if (valid && (unsigned)t < (unsigned)SEQ) {
            float z0 = 0.f, z1 = 0.f, z2 = 0.f, z3 = 0.f;
            if (isl0 && lane < 2) {
                const float* zp = g_Zin + (size_t)t * (4 * H) + myi;
                z0 = __ldcg(zp);          z1 = __ldcg(zp + H);
                z2 = __ldcg(zp + 2 * H);  z3 = __ldcg(zp + 3 * H);
            }

            float dwa[4] = {0, 0, 0, 0}, dwb[4] = {0, 0, 0, 0};
            float dua[4] = {0, 0, 0, 0}, dub[4] = {0, 0, 0, 0};
            if (isl0) {
#pragma unroll 4
                for (int kc = 0; kc < 32; kc += 2) {
                    uint2 a0 = haW[kc * 4 + tig];
                    uint2 b0 = bwp[kc * 32 + lane];
                    mma_fp8(dwa, a0.x, a0.y, b0.x, b0.y);
                    uint2 a1 = haW[(kc + 1) * 4 + tig];
                    uint2 b1 = bwp[(kc + 1) * 32 + lane];
                    mma_fp8(dwb, a1.x, a1.y, b1.x, b1.y);
                }
            } else {
#pragma unroll 2
                for (int kc = 0; kc < 32; kc += 2) {
                    uint2 aw0 = haW[kc * 4 + tig];
                    uint2 bw0 = bwp[kc * 32 + lane];
                    mma_fp8(dwa, aw0.x, aw0.y, bw0.x, bw0.y);
                    uint2 au0 = haU[kc * 4 + tig];
                    uint2 bu0 = bup[kc * 32 + lane];
                    mma_fp8(dua, au0.x, au0.y, bu0.x, bu0.y);
                    uint2 aw1 = haW[(kc + 1) * 4 + tig];
                    uint2 bw1 = bwp[(kc + 1) * 32 + lane];
                    mma_fp8(dwb, aw1.x, aw1.y, bw1.x, bw1.y);
                    uint2 au1 = haU[(kc + 1) * 4 + tig];
                    uint2 bu1 = bup[(kc + 1) * 32 + lane];
                    mma_fp8(dub, au1.x, au1.y, bu1.x, bu1.y);
                }
            }
            // row 0 of D: lane g holds cols 2g (c0) and 2g+1 (c1); col = 2*gate + rowsel
            float v0 = dwa[0] + dwb[0] + dua[0] + dub[0];  // rowsel 0 (i0),  gate = lane
            float v1 = dwa[1] + dwb[1] + dua[1] + dub[1];  // rowsel 1 (i0+1)
            float zf0 = __shfl_sync(0xffffffffu, v0, 0);
            float zg0 = __shfl_sync(0xffffffffu, v0, 1);
            float zq0 = __shfl_sync(0xffffffffu, v0, 2);
            float zc0 = __shfl_sync(0xffffffffu, v0, 3);
            float zf1 = __shfl_sync(0xffffffffu, v1, 0);
            float zg1 = __shfl_sync(0xffffffffu, v1, 1);
            float zq1 = __shfl_sync(0xffffffffu, v1, 2);
            float zc1 = __shfl_sync(0xffffffffu, v1, 3);

            if (lane < 2) {
                float Zf = (lane ? zf1 : zf0) + bfv + z0;
                float Zg = (lane ? zg1 : zg0) + bgv + z1;
                float Zq = (lane ? zq1 : zq0) + bqv + z2;
                float Zc = (lane ? zc1 : zc0) + bcv + z3;
                float F  = 1.f / (1.f + __expf(-Zf));
                float G  = 1.f / (1.f + __expf(-Zg));
                float Q  = 1.f / (1.f + __expf(-Zq));
                float C  = 1.f / (1.f + __expf(-Zc));
                s_state = fmaf(F, s_state, G * C);
                float hn = tanhf(s_state) * Q;
                g_h8[(step + 1) & 1][fragoff] =
                    (unsigned char)__nv_cvt_float_to_fp8(hn, __NV_SATFINITE, __NV_E4M3);
                if (t == SEQ - 1) out[bi] = hn;
            }
        }
        grid_barrier();
    }
}

// ------------------------- launch ---------------------------------------------
extern "C" void kernel_launch(void* const* d_in, const int* in_sizes, int n_in,
                              void* d_out, int out_size)
{
    const float* x   = (const float*)d_in[0];
    const float* Uf  = (const float*)d_in[1];
    const float* UHf = (const float*)d_in[2];
    const float* Wf  = (const float*)d_in[3];
    const float* Bf  = (const float*)d_in[4];
    const float* Ug  = (const float*)d_in[5];
    const float* UHg = (const float*)d_in[6];
    const float* Wg  = (const float*)d_in[7];
    const float* Bg  = (const float*)d_in[8];
    const float* Uq  = (const float*)d_in[9];
    const float* UHq = (const float*)d_in[10];
    const float* Wq  = (const float*)d_in[11];
    const float* Bq  = (const float*)d_in[12];
    const float* Uc  = (const float*)d_in[13];
    const float* UHc = (const float*)d_in[14];
    const float* Wc  = (const float*)d_in[15];
    const float* Bc  = (const float*)d_in[16];
    float* out = (float*)d_out;

    cudaFuncSetAttribute(lstm_main, cudaFuncAttributeMaxDynamicSharedMemorySize,
                         SMEM_MAX);

    prep_frag<<<3584, 1024>>>(Wf, Wg, Wq, Wc, UHf, UHg, UHq, UHc);
    init_state<<<1, 1024>>>();

    dim3 gg(4 * H / BN, SEQ / BM);
    gemm_zin<<<gg, 256>>>(x, Uf, Ug, Uq, Uc);

    lstm_main<<<NBLOCKS, NTHREADS, SMEM_MAX>>>(Bf, Bg, Bq, Bc, out);
}

// round 6
// speedup vs baseline: 1.3927x; 1.3927x over previous
#include <cuda_runtime.h>
#include <cuda_bf16.h>
#include <cuda_fp16.h>
#include <cuda_fp8.h>

#define SEQ 2048
#define H 1024
#define L 4
#define NSTEPS (SEQ + L - 1)
#define NBLOCKS 148
#define NTHREADS 1024
#define NTASKW 28           // warps 0..27 own tasks (7 l=0 rows + 21 l>0 rows)

// SMEM: 7*4KB + 21*8KB weights = 200704 B, + 8KB h-stage = 208896 B
#define SMEM_W_BYTES 200704
#define SMEM_BYTES   (SMEM_W_BYTES + 8192)

// ------------------------- device scratch (no allocs) -------------------------
__device__ unsigned char g_Wb8[(size_t)L * H * 4 * H];        // [l][i][gate][k] fp8
__device__ unsigned char g_UHb8[(size_t)(L - 1) * H * 4 * H]; // [l-1][i][gate][k] fp8
__device__ float g_Zin[(size_t)SEQ * 4 * H];                  // [t][gate*H + i]
__device__ __align__(16) __half g_hh[2][L * H];               // h, fp16, dbl-buffered
__device__ unsigned g_count;                                  // monotonic arrivals
__device__ unsigned g_done;                                   // monotonic steps done

// ------------------------- weight pack: fp32 -> fp8 e4m3 ----------------------
__global__ void prep_weights(const float* __restrict__ Wf, const float* __restrict__ Wg,
                             const float* __restrict__ Wq, const float* __restrict__ Wc,
                             const float* __restrict__ UHf, const float* __restrict__ UHg,
                             const float* __restrict__ UHq, const float* __restrict__ UHc)
{
    const size_t WTOT = (size_t)L * H * 4 * H;
    const size_t UTOT = (size_t)(L - 1) * H * 4 * H;
    size_t idx = (size_t)blockIdx.x * blockDim.x + threadIdx.x;
    if (idx < WTOT) {
        int k = (int)(idx & (H - 1));
        size_t r = idx >> 10;
        int g = (int)(r & 3);
        size_t li = r >> 2;                       // l*H + i
        const float* src = (g == 0) ? Wf : (g == 1) ? Wg : (g == 2) ? Wq : Wc;
        g_Wb8[idx] = (unsigned char)__nv_cvt_float_to_fp8(src[li * H + k],
                                                          __NV_SATFINITE, __NV_E4M3);
    } else if (idx < WTOT + UTOT) {
        size_t j = idx - WTOT;
        int k = (int)(j & (H - 1));
        size_t r = j >> 10;
        int g = (int)(r & 3);
        size_t li = r >> 2;                       // (l-1)*H + i
        const float* src = (g == 0) ? UHf : (g == 1) ? UHg : (g == 2) ? UHq : UHc;
        g_UHb8[j] = (unsigned char)__nv_cvt_float_to_fp8(src[li * H + k],
                                                         __NV_SATFINITE, __NV_E4M3);
    }
}

__global__ void init_state()
{
    int tid = threadIdx.x;
    for (int i = tid; i < L * H; i += blockDim.x) {
        g_hh[0][i] = __float2half(0.f);
        g_hh[1][i] = __float2half(0.f);
    }
    if (tid == 0) { g_count = 0u; g_done = 0u; }
}

// ------------------------- Zin GEMM: C[t][g*H+i] = sum_k x[t][k] * U_g[i][k] ---
#define BM 128
#define BN 128
#define BK 16
__global__ __launch_bounds__(256) void gemm_zin(
    const float* __restrict__ A,                  // x [SEQ][H]
    const float* __restrict__ U0, const float* __restrict__ U1,
    const float* __restrict__ U2, const float* __restrict__ U3)
{
    __shared__ __align__(16) float As[BK][BM];
    __shared__ __align__(16) float Bs[BK][BN];
    const int tid = threadIdx.x;
    const int bm = blockIdx.y * BM;
    const int bn = blockIdx.x * BN;
    const int gate = bn >> 10;                    // 128-wide tile never spans gates
    const float* Bp = ((gate == 0) ? U0 : (gate == 1) ? U1 : (gate == 2) ? U2 : U3)
                      + (size_t)(bn & (H - 1)) * H;
    const int lr = tid & 63;
    const int gq = tid >> 6;                      // 0..3 (k-quad)
    const int tx = tid & 15, ty = tid >> 4;

    float acc[8][8];
#pragma unroll
    for (int i = 0; i < 8; ++i)
#pragma unroll
        for (int j = 0; j < 8; ++j) acc[i][j] = 0.f;

    for (int k0 = 0; k0 < H; k0 += BK) {
        float4 a0 = *(const float4*)(A + (size_t)(bm + lr) * H + k0 + gq * 4);
        float4 a1 = *(const float4*)(A + (size_t)(bm + lr + 64) * H + k0 + gq * 4);
        float4 b0 = *(const float4*)(Bp + (size_t)lr * H + k0 + gq * 4);
        float4 b1 = *(const float4*)(Bp + (size_t)(lr + 64) * H + k0 + gq * 4);
        As[gq * 4 + 0][lr] = a0.x; As[gq * 4 + 1][lr] = a0.y;
        As[gq * 4 + 2][lr] = a0.z; As[gq * 4 + 3][lr] = a0.w;
        As[gq * 4 + 0][lr + 64] = a1.x; As[gq * 4 + 1][lr + 64] = a1.y;
        As[gq * 4 + 2][lr + 64] = a1.z; As[gq * 4 + 3][lr + 64] = a1.w;
        Bs[gq * 4 + 0][lr] = b0.x; Bs[gq * 4 + 1][lr] = b0.y;
        Bs[gq * 4 + 2][lr] = b0.z; Bs[gq * 4 + 3][lr] = b0.w;
        Bs[gq * 4 + 0][lr + 64] = b1.x; Bs[gq * 4 + 1][lr + 64] = b1.y;
        Bs[gq * 4 + 2][lr + 64] = b1.z; Bs[gq * 4 + 3][lr + 64] = b1.w;
        __syncthreads();
#pragma unroll
        for (int kk = 0; kk < BK; ++kk) {
            float4 a0r = *(const float4*)&As[kk][ty * 8];
            float4 a1r = *(const float4*)&As[kk][ty * 8 + 4];
            float4 b0r = *(const float4*)&Bs[kk][tx * 8];
            float4 b1r = *(const float4*)&Bs[kk][tx * 8 + 4];
            float ar[8] = {a0r.x, a0r.y, a0r.z, a0r.w, a1r.x, a1r.y, a1r.z, a1r.w};
            float br[8] = {b0r.x, b0r.y, b0r.z, b0r.w, b1r.x, b1r.y, b1r.z, b1r.w};
#pragma unroll
            for (int i = 0; i < 8; ++i)
#pragma unroll
                for (int j = 0; j < 8; ++j)
                    acc[i][j] = fmaf(ar[i], br[j], acc[i][j]);
        }
        __syncthreads();
    }
#pragma unroll
    for (int i = 0; i < 8; ++i) {
        int m = bm + ty * 8 + i;
        float* crow = g_Zin + (size_t)m * (4 * H) + bn + tx * 8;
#pragma unroll
        for (int j = 0; j < 8; j += 4) {
            *(float4*)(crow + j) = make_float4(acc[i][j], acc[i][j + 1],
                                               acc[i][j + 2], acc[i][j + 3]);
        }
    }
}

// ------------------------- merged monotonic grid barrier -----------------------
// Single release-add counter (never reset). Last arriver publishes done=step+1
// and skips polling. Waiters poll with ~100cyc dependent-ALU backoff to keep
// L2 poll traffic off the arrival path.
__device__ __forceinline__ void arrive_wait(unsigned step)
{
    __syncthreads();
    if (threadIdx.x == 0) {
        unsigned arrived;
        asm volatile("atom.release.gpu.add.u32 %0, [%1], 1;"
                     : "=r"(arrived) : "l"(&g_count) : "memory");
        const unsigned target = (step + 1u) * NBLOCKS;
        if (arrived == target - 1u) {
            asm volatile("st.release.gpu.u32 [%0], %1;"
                         :: "l"(&g_done), "r"(step + 1u) : "memory");
        } else {
            unsigned cur;
            asm volatile("ld.acquire.gpu.u32 %0, [%1];"
                         : "=r"(cur) : "l"(&g_done) : "memory");
            while (cur < step + 1u) {
                unsigned junk = cur;
#pragma unroll
                for (int z = 0; z < 24; ++z)
                    asm volatile("add.u32 %0, %0, 1;" : "+r"(junk));
                asm volatile("ld.acquire.gpu.u32 %0, [%1];"
                             : "=r"(cur) : "l"(&g_done) : "memory");
            }
        }
    }
    __syncthreads();
}

// ------------------------- fp8 -> half2 convert --------------------------------
__device__ __forceinline__ __half2 cvt_e4m3x2(unsigned short v)
{
    unsigned r;
    asm("cvt.rn.f16x2.e4m3x2 %0, %1;" : "=r"(r) : "h"(v));
    return *reinterpret_cast<__half2*>(&r);
}

// One 4-gate fp8 row (SMEM) dotted against a staged h vector (SMEM, split layout).
__device__ __forceinline__ void mv_smem(const uint4* __restrict__ wsm,
                                        const uint4* __restrict__ hsm,
                                        int lane, __half2 acc2[4])
{
#pragma unroll
    for (int c = 0; c < 2; ++c) {
        uint4 ha = hsm[(c * 2 + 0) * 32 + lane];
        uint4 hb = hsm[(c * 2 + 1) * 32 + lane];
        __half2 hv[8];
        *reinterpret_cast<uint4*>(&hv[0]) = ha;
        *reinterpret_cast<uint4*>(&hv[4]) = hb;
#pragma unroll
        for (int g = 0; g < 4; ++g) {
            uint4 w = wsm[g * 64 + c * 32 + lane];
            const unsigned short* ws = reinterpret_cast<const unsigned short*>(&w);
#pragma unroll
            for (int j = 0; j < 8; ++j)
                acc2[g] = __hfma2(cvt_e4m3x2(ws[j]), hv[j], acc2[g]);
        }
    }
}

// ------------------------- persistent wavefront LSTM (SMEM-resident weights) --
__global__ __launch_bounds__(NTHREADS, 1) void lstm_main(
    const float* __restrict__ Bf, const float* __restrict__ Bg,
    const float* __restrict__ Bq, const float* __restrict__ Bc,
    float* __restrict__ out)
{
    extern __shared__ __align__(16) unsigned char smem[];
    unsigned char* sh_h = smem + SMEM_W_BYTES;    // 4 vectors x 2048 B (split layout)

    const int tid  = threadIdx.x;
    const int lane = tid & 31;
    const int w    = tid >> 5;

    // ---- static task assignment: warp -> (l, i) ----
    int l = -1, i = 0, woff = 0;
    bool valid = false;
    if (w < 7) {
        l = 0; i = blockIdx.x * 7 + w; woff = w * 4096;
        valid = (i < H);
    } else if (w < NTASKW) {
        int j = blockIdx.x * 21 + (w - 7);
        l = 1 + (j >> 10); i = j & (H - 1);
        woff = 28672 + (w - 7) * 8192;
        valid = (j < 3 * H);
    }
    const int bi = (valid ? l * H + i : 0);

    // ---- copy this warp's weights into SMEM (once) ----
    if (valid) {
        const uint4* srcW = reinterpret_cast<const uint4*>(g_Wb8 + (size_t)bi * 4096);
        uint4* dstW = reinterpret_cast<uint4*>(smem + woff);
#pragma unroll 4
        for (int m = lane; m < 256; m += 32) dstW[m] = __ldcg(&srcW[m]);
        if (l > 0) {
            const uint4* srcU = reinterpret_cast<const uint4*>(
                g_UHb8 + (size_t)((l - 1) * H + i) * 4096);
            uint4* dstU = reinterpret_cast<uint4*>(smem + woff + 4096);
#pragma unroll 4
            for (int m = lane; m < 256; m += 32) dstU[m] = __ldcg(&srcU[m]);
        }
    }

    // ---- per-task constants & state ----
    // bias for "my" gate: lane g in 0..3 handles gate g in the epilogue
    float bias_g = 0.f;
    if (valid) {
        float b0 = Bf[bi], b1 = Bg[bi], b2 = Bq[bi], b3 = Bc[bi];
        bias_g = (lane == 0) ? b0 : (lane == 1) ? b1 : (lane == 2) ? b2 : b3;
    }
    float s_state = 0.f;

    const uint4* wsm = reinterpret_cast<const uint4*>(smem + woff);
    const uint4* usm = reinterpret_cast<const uint4*>(smem + woff + 4096);
    __syncthreads();

    for (int step = 0; step < NSTEPS; ++step) {
        const int t = step - l;
        const bool active = valid && ((unsigned)t < (unsigned)SEQ);

        // ---- Zin prefetch (recurrence-independent): lanes 0..3 of l==0 warps ----
        float zin_g = 0.f;
        if (active && l == 0 && lane < 4)
            zin_g = __ldcg(g_Zin + (size_t)t * (4 * H) + lane * H + i);

        // ---- stage previous-step h (4 vectors, fp16) into SMEM split layout ----
        if (tid < 512) {
            const uint4* hg = reinterpret_cast<const uint4*>(g_hh[step & 1]);
            uint4 val = __ldcg(hg + tid);
            int v = tid >> 7, m = tid & 127;
            int dst = (m >> 6) * 64 + (m & 1) * 32 + ((m & 63) >> 1);
            reinterpret_cast<uint4*>(sh_h)[v * 128 + dst] = val;
        }
        __syncthreads();

        if (active) {
            __half2 acc2[4];
            const __half2 hz = __float2half2_rn(0.f);
            acc2[0] = hz; acc2[1] = hz; acc2[2] = hz; acc2[3] = hz;

            mv_smem(wsm, reinterpret_cast<const uint4*>(sh_h + l * 2048), lane, acc2);
            if (l > 0)
                mv_smem(usm, reinterpret_cast<const uint4*>(sh_h + (l - 1) * 2048),
                        lane, acc2);

            float acc[4];
#pragma unroll
            for (int g = 0; g < 4; ++g) {
                float2 f = __half22float2(acc2[g]);
                acc[g] = f.x + f.y;
            }
#pragma unroll
            for (int off = 16; off > 0; off >>= 1) {
                acc[0] += __shfl_xor_sync(0xffffffffu, acc[0], off);
                acc[1] += __shfl_xor_sync(0xffffffffu, acc[1], off);
                acc[2] += __shfl_xor_sync(0xffffffffu, acc[2], off);
                acc[3] += __shfl_xor_sync(0xffffffffu, acc[3], off);
            }

            // ---- parallel epilogue: lane g computes sigmoid of gate g ----
            float zg = (lane == 0) ? acc[0] : (lane == 1) ? acc[1]
                     : (lane == 2) ? acc[2] : acc[3];
            float Z = zg + bias_g + zin_g;
            float sig = 1.f / (1.f + __expf(-Z));
            float F = __shfl_sync(0xffffffffu, sig, 0);
            float G = __shfl_sync(0xffffffffu, sig, 1);
            float Q = __shfl_sync(0xffffffffu, sig, 2);
            float C = __shfl_sync(0xffffffffu, sig, 3);

            if (lane == 0) {
                s_state = fmaf(F, s_state, G * C);
                float hn = tanhf(s_state) * Q;
                __half hh = __float2half_rn(hn);
                unsigned short hb16 = *reinterpret_cast<unsigned short*>(&hh);
                asm volatile("st.global.cg.u16 [%0], %1;"
                             :: "l"(&g_hh[(step + 1) & 1][bi]), "h"(hb16));
                if (t == SEQ - 1) out[bi] = hn;
            }
        }
        if (step < NSTEPS - 1) arrive_wait((unsigned)step);
    }
}

// ------------------------- launch ---------------------------------------------
extern "C" void kernel_launch(void* const* d_in, const int* in_sizes, int n_in,
                              void* d_out, int out_size)
{
    const float* x   = (const float*)d_in[0];
    const float* Uf  = (const float*)d_in[1];
    const float* UHf = (const float*)d_in[2];
    const float* Wf  = (const float*)d_in[3];
    const float* Bf  = (const float*)d_in[4];
    const float* Ug  = (const float*)d_in[5];
    const float* UHg = (const float*)d_in[6];
    const float* Wg  = (const float*)d_in[7];
    const float* Bg  = (const float*)d_in[8];
    const float* Uq  = (const float*)d_in[9];
    const float* UHq = (const float*)d_in[10];
    const float* Wq  = (const float*)d_in[11];
    const float* Bq  = (const float*)d_in[12];
    const float* Uc  = (const float*)d_in[13];
    const float* UHc = (const float*)d_in[14];
    const float* Wc  = (const float*)d_in[15];
    const float* Bc  = (const float*)d_in[16];
    float* out = (float*)d_out;

    cudaFuncSetAttribute(lstm_main, cudaFuncAttributeMaxDynamicSharedMemorySize,
                         SMEM_BYTES);

    const size_t TOTAL = (size_t)L * H * 4 * H + (size_t)(L - 1) * H * 4 * H;
    int pb = (int)((TOTAL + 1023) / 1024);
    prep_weights<<<pb, 1024>>>(Wf, Wg, Wq, Wc, UHf, UHg, UHq, UHc);
    init_state<<<1, 1024>>>();

    dim3 gg(4 * H / BN, SEQ / BM);
    gemm_zin<<<gg, 256>>>(x, Uf, Ug, Uq, Uc);

    lstm_main<<<NBLOCKS, NTHREADS, SMEM_BYTES>>>(Bf, Bg, Bq, Bc, out);
}